// round 5
// baseline (speedup 1.0000x reference)
#include <cuda_runtime.h>
#include <math.h>

#define BATCH 32768
#define SEQ 50
#define D 16
#define XDIM 112

// ---------------- scratch (no allocations allowed) ----------------
__device__ float g_x[BATCH * XDIM];   // [0:48) singles, [48:112) pooled (pre-BN)
__device__ float g_sum[64];
__device__ float g_sq[64];

// ---------------- f32x2 helpers ----------------
__device__ __forceinline__ unsigned long long ffma2(unsigned long long a,
                                                    unsigned long long b,
                                                    unsigned long long c) {
    unsigned long long d;
    asm("fma.rn.f32x2 %0, %1, %2, %3;" : "=l"(d) : "l"(a), "l"(b), "l"(c));
    return d;
}
__device__ __forceinline__ unsigned long long pack2(float lo, float hi) {
    unsigned long long d;
    asm("mov.b64 %0, {%1, %2};" : "=l"(d) : "f"(lo), "f"(hi));
    return d;
}
__device__ __forceinline__ void unpack2(unsigned long long v, float& lo, float& hi) {
    asm("mov.b64 {%0, %1}, %2;" : "=f"(lo), "=f"(hi) : "l"(v));
}

// ---------------- kernel 0: zero stats (graph replays!) ----------------
__global__ void k_zero() {
    int t = threadIdx.x;
    if (t < 64) { g_sum[t] = 0.f; g_sq[t] = 0.f; }
}

// ---------------- kernel 1: feature-parallel gather + pool + BN stats ----------------
// block = 256 thr = 4 features (t>>6) x 4 rows ((t>>4)&3) x 16 lanes (t&15)
// warp = one feature, two rows -> uniform code path per warp
__global__ void __launch_bounds__(256) k_gather(
    const int* __restrict__ user_id, const int* __restrict__ movie_id, const int* __restrict__ year,
    const int* __restrict__ ug, const int* __restrict__ urb,
    const int* __restrict__ mg, const int* __restrict__ mt,
    const int* __restrict__ ug_m, const int* __restrict__ urb_m,
    const int* __restrict__ mg_m, const int* __restrict__ mt_m,
    const float* __restrict__ Eu, const float* __restrict__ Em, const float* __restrict__ Et,
    const float* __restrict__ Eg, const float* __restrict__ Ey,
    const float* __restrict__ Am)
{
    __shared__ float s_sum[64], s_sq[64];
    int t = threadIdx.x;
    if (t < 64) { s_sum[t] = 0.f; s_sq[t] = 0.f; }
    __syncthreads();

    int lane = t & 15;
    int row_local = (t >> 4) & 3;
    int f = t >> 6;
    int r = blockIdx.x * 4 + row_local;
    unsigned gm = 0xFFFFu << (t & 16);   // 16-lane shuffle group mask

    float* xrow = g_x + r * XDIM;
    float p;

    if (f == 0) {
        // single: userId ; pool: sum over user_genre (genre table)
        xrow[lane] = Eu[user_id[r] * D + lane];
        int cnt = ug_m[r];
        const int* ids = ug + r * SEQ;
        float acc = 0.f;
        #pragma unroll 4
        for (int i = 0; i < cnt; i++) acc += Eg[ids[i] * D + lane];
        p = acc;
    } else if (f == 1) {
        // single: movieId ; pool: atten over urb (movie table)
        xrow[16 + lane] = Em[movie_id[r] * D + lane];
        int cnt = urb_m[r];
        const int* ids = urb + r * SEQ;
        float num = 0.f, den = (float)(SEQ - cnt);  // masked slots contribute exp(0)=1
        #pragma unroll 4
        for (int i = 0; i < cnt; i++) {
            int id = ids[i];
            float w = expf(Am[id]);
            num = fmaf(Em[id * D + lane], w, num);
            den += w;
        }
        p = num / den;
    } else if (f == 2) {
        // single: year ; pool: max-L2 over movie_genre (genre table)
        xrow[32 + lane] = Ey[year[r] * D + lane];
        int cnt = mg_m[r];
        const int* ids = mg + r * SEQ;
        // lane-parallel argmax: lane j scores positions j, j+16, j+32, (j+48)
        float bl2 = 0.f; int bpos = SEQ;
        #pragma unroll
        for (int base = 0; base < SEQ; base += 16) {
            int pos = base + lane;
            if (pos < cnt) {
                const float4* rp = (const float4*)(Eg + ids[pos] * D);
                float4 a = rp[0], b = rp[1], c = rp[2], d4 = rp[3];
                float l2 = a.x*a.x + a.y*a.y + a.z*a.z + a.w*a.w
                         + b.x*b.x + b.y*b.y + b.z*b.z + b.w*b.w
                         + c.x*c.x + c.y*c.y + c.z*c.z + c.w*c.w
                         + d4.x*d4.x + d4.y*d4.y + d4.z*d4.z + d4.w*d4.w;
                if (l2 > bl2 || (l2 == bl2 && pos < bpos)) { bl2 = l2; bpos = pos; }
            }
        }
        // single cross-lane argmax reduce (first-occurrence tie-break)
        #pragma unroll
        for (int off = 8; off; off >>= 1) {
            float ol2 = __shfl_xor_sync(gm, bl2, off, 16);
            int opos = __shfl_xor_sync(gm, bpos, off, 16);
            if (ol2 > bl2 || (ol2 == bl2 && opos < bpos)) { bl2 = ol2; bpos = opos; }
        }
        p = (bl2 > 0.f) ? Eg[ids[bpos] * D + lane] : 0.f;
    } else {
        // pool: korder over movie_tag (tag table)
        // s*s must be separately-rounded (no FMA contraction with -ss): for
        // cnt==1 the reference gets exact 0 before normalization.
        int cnt = mt_m[r];
        const int* ids = mt + r * SEQ;
        float s = 0.f, ss = 0.f;
        #pragma unroll 4
        for (int i = 0; i < cnt; i++) {
            float e = Et[ids[i] * D + lane];
            s += e;
            ss = __fmaf_rn(e, e, ss);
        }
        float s2 = __fmul_rn(s, s);
        float v = 0.5f * __fadd_rn(s2, -ss);
        float n2 = __fmul_rn(v, v);
        n2 += __shfl_xor_sync(gm, n2, 8, 16);
        n2 += __shfl_xor_sync(gm, n2, 4, 16);
        n2 += __shfl_xor_sync(gm, n2, 2, 16);
        n2 += __shfl_xor_sync(gm, n2, 1, 16);
        float n = fmaxf(sqrtf(n2), 1e-12f);
        p = v / n;
    }

    xrow[48 + 16 * f + lane] = p;
    atomicAdd(&s_sum[16 * f + lane], p);
    atomicAdd(&s_sq[16 * f + lane], p * p);
    __syncthreads();
    if (t < 64) {
        atomicAdd(&g_sum[t], s_sum[t]);
        atomicAdd(&g_sq[t],  s_sq[t]);
    }
}

// ---------------- kernel 2: BN finalize (in-block) + MLP, 4 threads/row ----------------
// block = 128 thr = 32 rows x 4 quads; each quad-thread computes 16 of 64 L1 outs
__global__ void __launch_bounds__(128) k_mlp(
    const float* __restrict__ gamma, const float* __restrict__ beta,
    const float* __restrict__ W1, const float* __restrict__ b1,
    const float* __restrict__ W2, const float* __restrict__ b2,
    const float* __restrict__ W3, const float* __restrict__ b3,
    float* __restrict__ out)
{
    __shared__ __align__(16) float W1s[112 * 64];   // 28 KB
    __shared__ __align__(16) float W2s[64 * 32];    // 8 KB
    __shared__ float h1s[32 * 65];                  // padded: 8.3 KB
    __shared__ float W3s[32], b2s[32];
    __shared__ float As[64], Bs[64], b1s[64];

    int t = threadIdx.x;
    for (int i = t; i < 112 * 64; i += 128) W1s[i] = W1[i];
    for (int i = t; i < 64 * 32; i += 128)  W2s[i] = W2[i];
    if (t < 32) { W3s[t] = W3[t]; b2s[t] = b2[t]; }
    if (t < 64) {
        b1s[t] = b1[t];
        const float invB = 1.f / (float)BATCH;
        float mean = g_sum[t] * invB;
        float var  = g_sq[t] * invB - mean * mean;
        float a = gamma[t] * rsqrtf(var + 1e-5f);
        As[t] = a;
        Bs[t] = beta[t] - mean * a;
    }
    __syncthreads();

    int row_local = t >> 2;
    int q = t & 3;
    int r = blockIdx.x * 32 + row_local;
    const float4* xr4 = (const float4*)(g_x + r * XDIM);

    // ---- layer 1: 112 -> this quad's 16 outputs (8 f32x2 accumulators) ----
    unsigned long long h[8];
    #pragma unroll
    for (int jp = 0; jp < 8; jp++)
        h[jp] = pack2(b1s[16 * q + 2 * jp], b1s[16 * q + 2 * jp + 1]);

    #pragma unroll
    for (int kt = 0; kt < 14; kt++) {
        float4 a4 = xr4[2 * kt];
        float4 b4 = xr4[2 * kt + 1];
        float xr[8] = {a4.x, a4.y, a4.z, a4.w, b4.x, b4.y, b4.z, b4.w};
        int kbase = kt * 8;
        if (kbase >= 48) {   // BN on pooled section only
            #pragma unroll
            for (int u = 0; u < 8; u++) {
                int c = kbase + u - 48;
                xr[u] = xr[u] * As[c] + Bs[c];
            }
        }
        #pragma unroll
        for (int u = 0; u < 8; u++) {
            unsigned long long xx = pack2(xr[u], xr[u]);
            const unsigned long long* wrow =
                (const unsigned long long*)(W1s + (kbase + u) * 64 + 16 * q);
            #pragma unroll
            for (int jp = 0; jp < 8; jp++) h[jp] = ffma2(xx, wrow[jp], h[jp]);
        }
    }

    // relu -> smem exchange
    float* hrow = h1s + row_local * 65;
    #pragma unroll
    for (int jp = 0; jp < 8; jp++) {
        float lo, hi; unpack2(h[jp], lo, hi);
        hrow[16 * q + 2 * jp]     = fmaxf(lo, 0.f);
        hrow[16 * q + 2 * jp + 1] = fmaxf(hi, 0.f);
    }
    __syncthreads();

    // ---- layer 2: 64 -> this quad's 8 outputs ----
    unsigned long long h2[4];
    #pragma unroll
    for (int jp = 0; jp < 4; jp++)
        h2[jp] = pack2(b2s[8 * q + 2 * jp], b2s[8 * q + 2 * jp + 1]);
    #pragma unroll 8
    for (int k = 0; k < 64; k++) {
        float x = hrow[k];
        unsigned long long xx = pack2(x, x);
        const unsigned long long* wrow =
            (const unsigned long long*)(W2s + k * 32 + 8 * q);
        #pragma unroll
        for (int jp = 0; jp < 4; jp++) h2[jp] = ffma2(xx, wrow[jp], h2[jp]);
    }

    // ---- layer 3 partial + quad reduce + sigmoid ----
    float z = 0.f;
    #pragma unroll
    for (int jp = 0; jp < 4; jp++) {
        float lo, hi; unpack2(h2[jp], lo, hi);
        z += fmaxf(lo, 0.f) * W3s[8 * q + 2 * jp]
           + fmaxf(hi, 0.f) * W3s[8 * q + 2 * jp + 1];
    }
    z += __shfl_xor_sync(0xFFFFFFFFu, z, 1);
    z += __shfl_xor_sync(0xFFFFFFFFu, z, 2);
    if (q == 0) out[r] = 1.f / (1.f + expf(-(z + b3[0])));
}

// ---------------- launch ----------------
extern "C" void kernel_launch(void* const* d_in, const int* in_sizes, int n_in,
                              void* d_out, int out_size) {
    const int* user_id  = (const int*)d_in[0];
    const int* movie_id = (const int*)d_in[1];
    const int* year     = (const int*)d_in[2];
    const int* ug       = (const int*)d_in[3];
    const int* urb      = (const int*)d_in[4];
    const int* mg       = (const int*)d_in[5];
    const int* mt       = (const int*)d_in[6];
    const int* ug_m     = (const int*)d_in[7];
    const int* urb_m    = (const int*)d_in[8];
    const int* mg_m     = (const int*)d_in[9];
    const int* mt_m     = (const int*)d_in[10];
    const float* Eu     = (const float*)d_in[11];
    const float* Em     = (const float*)d_in[12];
    const float* Et     = (const float*)d_in[13];
    const float* Eg     = (const float*)d_in[14];
    const float* Ey     = (const float*)d_in[15];
    const float* Am     = (const float*)d_in[16];
    const float* gamma  = (const float*)d_in[19];
    const float* beta   = (const float*)d_in[20];
    const float* W1     = (const float*)d_in[21];
    const float* b1     = (const float*)d_in[22];
    const float* W2     = (const float*)d_in[23];
    const float* b2     = (const float*)d_in[24];
    const float* W3     = (const float*)d_in[25];
    const float* b3     = (const float*)d_in[26];

    k_zero<<<1, 64>>>();
    k_gather<<<BATCH / 4, 256>>>(user_id, movie_id, year, ug, urb, mg, mt,
                                 ug_m, urb_m, mg_m, mt_m,
                                 Eu, Em, Et, Eg, Ey, Am);
    k_mlp<<<BATCH / 32, 128>>>(gamma, beta, W1, b1, W2, b2, W3, b3, (float*)d_out);
}